// round 15
// baseline (speedup 1.0000x reference)
#include <cuda_runtime.h>
#include <cuda_fp16.h>
#include <cuda_bf16.h>
#include <math_constants.h>
#include <cstdint>
#include <cstring>

// Problem constants (fixed by reference setup_inputs)
#define BATCH   2
#define SEQ     4096
#define DMODEL  768
#define NHEADS  12
#define DHEAD   64
#define BT      (BATCH * SEQ)        // 8192
#define C3      (3 * DMODEL)         // 2304

// Scratch (device globals: allocation-free per harness rules)
__device__ __half g_x16[(size_t)BT * DMODEL];      // x fp16
__device__ __half g_wq16[(size_t)DMODEL * C3];     // W_qkv fp16
__device__ __half g_wp16[(size_t)DMODEL * DMODEL]; // W_proj fp16
__device__ __half g_q16[(size_t)BT * DMODEL];      // Q fp16
__device__ __half g_k16[(size_t)BT * DMODEL];      // K fp16
__device__ __half g_v16[(size_t)BT * DMODEL];      // V fp16
__device__ __half g_at16[(size_t)BT * DMODEL];     // att out fp16

// ---------------------------------------------------------------------------
// PTX helpers
// ---------------------------------------------------------------------------
__device__ __forceinline__ float fast_exp2(float x) {
    float y;
    asm("ex2.approx.f32 %0, %1;" : "=f"(y) : "f"(x));
    return y;
}

// Packed fp16x2 exp2 (one MUFU op for two values)
__device__ __forceinline__ uint32_t ex2_f16x2(uint32_t a) {
    uint32_t d;
    asm("ex2.approx.f16x2 %0, %1;" : "=r"(d) : "r"(a));
    return d;
}

__device__ __forceinline__ uint32_t h2_as_u32(__half2 h) {
    uint32_t r; memcpy(&r, &h, 4); return r;
}
__device__ __forceinline__ __half2 u32_as_h2(uint32_t r) {
    __half2 h; memcpy(&h, &r, 4); return h;
}

__device__ __forceinline__ void mma_f16(float c[4], const uint32_t a[4],
                                        uint32_t b0, uint32_t b1) {
    asm volatile(
        "mma.sync.aligned.m16n8k16.row.col.f32.f16.f16.f32 "
        "{%0,%1,%2,%3},{%4,%5,%6,%7},{%8,%9},{%0,%1,%2,%3};"
        : "+f"(c[0]), "+f"(c[1]), "+f"(c[2]), "+f"(c[3])
        : "r"(a[0]), "r"(a[1]), "r"(a[2]), "r"(a[3]), "r"(b0), "r"(b1));
}

__device__ __forceinline__ void ldmatrix_x4(uint32_t& r0, uint32_t& r1,
                                            uint32_t& r2, uint32_t& r3,
                                            uint32_t addr) {
    asm volatile(
        "ldmatrix.sync.aligned.m8n8.x4.shared.b16 {%0,%1,%2,%3}, [%4];"
        : "=r"(r0), "=r"(r1), "=r"(r2), "=r"(r3)
        : "r"(addr));
}

__device__ __forceinline__ void ldmatrix_x4_trans(uint32_t& r0, uint32_t& r1,
                                                  uint32_t& r2, uint32_t& r3,
                                                  uint32_t addr) {
    asm volatile(
        "ldmatrix.sync.aligned.m8n8.x4.trans.shared.b16 {%0,%1,%2,%3}, [%4];"
        : "=r"(r0), "=r"(r1), "=r"(r2), "=r"(r3)
        : "r"(addr));
}

__device__ __forceinline__ void cp_async16(uint32_t smem, const void* gmem) {
    asm volatile("cp.async.cg.shared.global [%0], [%1], 16;"
                 :: "r"(smem), "l"(gmem));
}
__device__ __forceinline__ void cp_commit() {
    asm volatile("cp.async.commit_group;");
}

// ---------------------------------------------------------------------------
// fp32 -> fp16 convert (streaming). One thread per float4.
// ---------------------------------------------------------------------------
__global__ __launch_bounds__(256)
void cvt16_kernel(const float* __restrict__ src, __half* __restrict__ dst)
{
    const size_t i4 = (size_t)blockIdx.x * 256 + threadIdx.x;
    float4 v = reinterpret_cast<const float4*>(src)[i4];
    __half h[4] = {__float2half_rn(v.x), __float2half_rn(v.y),
                   __float2half_rn(v.z), __float2half_rn(v.w)};
    uint2 u;
    memcpy(&u, h, 8);
    *reinterpret_cast<uint2*>(&dst[i4 * 4]) = u;
}

// ---------------------------------------------------------------------------
// fp16 GEMM (fp32 accum), 4-stage cp.async ring, ONE barrier per stage.
// mode 0: fp32 C store (+bias).
// mode 1: QKV fused epilogue — writes Q/K/V segments directly as fp16.
// ---------------------------------------------------------------------------
#define AST2 24     // halves per A smem row (16 + 8 pad); conflict-free
#define BST2 136    // halves per B smem row (128 + 8 pad)
#define NSTG 4      // pipeline stages

__global__ __launch_bounds__(256, 2)
void gemm_f16_async_kernel(const __half* __restrict__ A16,
                           const __half* __restrict__ B16,
                           const float* __restrict__ bias,
                           float* __restrict__ Cmat,
                           int M, int N, int K,
                           int mode,
                           __half* __restrict__ q_out,
                           __half* __restrict__ k_out,
                           __half* __restrict__ v_out)
{
    __shared__ __half As[NSTG][128 * AST2];
    __shared__ __half Bs[NSTG][16 * BST2];

    const int tid  = threadIdx.x;
    const int warp = tid >> 5;
    const int lane = tid & 31;
    const int g    = lane >> 2;
    const int tg   = lane & 3;

    const int brow = blockIdx.y * 128;
    const int bcol = blockIdx.x * 128;
    const int wm   = (warp >> 2) * 64;
    const int wn   = (warp & 3) * 32;

    uint32_t sA[NSTG], sB[NSTG];
    #pragma unroll
    for (int i = 0; i < NSTG; i++) {
        sA[i] = (uint32_t)__cvta_generic_to_shared(As[i]);
        sB[i] = (uint32_t)__cvta_generic_to_shared(Bs[i]);
    }

    const int a_row = tid >> 1;          // 0..127
    const int a_c   = (tid & 1) * 8;     // halves 0 or 8
    const int b_row = tid >> 4;          // 0..15
    const int b_c   = (tid & 15) * 8;    // 0..120

    float acc[4][4][4];
    #pragma unroll
    for (int mt = 0; mt < 4; mt++)
        #pragma unroll
        for (int nt = 0; nt < 4; nt++)
            #pragma unroll
            for (int j = 0; j < 4; j++) acc[mt][nt][j] = 0.f;

    const int n_stages = K / 16;

    auto issue = [&](int s) {
        const int k0  = s * 16;
        const int buf = s & (NSTG - 1);
        cp_async16(sA[buf] + (a_row * AST2 + a_c) * 2,
                   &A16[(size_t)(brow + a_row) * K + k0 + a_c]);
        cp_async16(sB[buf] + (b_row * BST2 + b_c) * 2,
                   &B16[(size_t)(k0 + b_row) * N + bcol + b_c]);
        cp_commit();
    };

    // Prologue: 3 stages in flight
    issue(0); issue(1); issue(2);

    for (int s = 0; s < n_stages; s++) {
        const int buf = s & (NSTG - 1);
        // Outstanding groups: s, s+1, s+2 (some may be empty commits at tail)
        asm volatile("cp.async.wait_group 2;");
        __syncthreads();   // data s ready for all; all warps past compute(s-1)
        if (s + 3 < n_stages) issue(s + 3); else cp_commit();

        uint32_t bf[2][4];
        #pragma unroll
        for (int ng = 0; ng < 2; ng++) {
            uint32_t boff = (uint32_t)(
                (lane & 15) * BST2 + wn + ng * 16 + ((lane & 16) ? 8 : 0)) * 2u;
            ldmatrix_x4_trans(bf[ng][0], bf[ng][1], bf[ng][2], bf[ng][3],
                              sB[buf] + boff);
        }
        #pragma unroll
        for (int mt = 0; mt < 4; mt++) {
            uint32_t af[4];
            uint32_t aoff = (uint32_t)(
                (wm + mt * 16 + (lane & 15)) * AST2 + ((lane & 16) ? 8 : 0)) * 2u;
            ldmatrix_x4(af[0], af[1], af[2], af[3], sA[buf] + aoff);
            #pragma unroll
            for (int ng = 0; ng < 2; ng++) {
                #pragma unroll
                for (int hh = 0; hh < 2; hh++) {
                    mma_f16(acc[mt][ng * 2 + hh], af,
                            bf[ng][2 * hh], bf[ng][2 * hh + 1]);
                }
            }
        }
    }

    if (mode == 0) {
        #pragma unroll
        for (int mt = 0; mt < 4; mt++) {
            #pragma unroll
            for (int nt = 0; nt < 4; nt++) {
                int row0 = brow + wm + mt * 16 + g;
                int col  = bcol + wn + nt * 8 + 2 * tg;
                float b0 = bias[col], b1 = bias[col + 1];
                float2 v0 = make_float2(acc[mt][nt][0] + b0, acc[mt][nt][1] + b1);
                float2 v1 = make_float2(acc[mt][nt][2] + b0, acc[mt][nt][3] + b1);
                *reinterpret_cast<float2*>(&Cmat[(size_t)row0 * N + col])       = v0;
                *reinterpret_cast<float2*>(&Cmat[(size_t)(row0 + 8) * N + col]) = v1;
            }
        }
    } else {
        const int seg = bcol / DMODEL;   // 0=Q, 1=K, 2=V (uniform per block)
        __half* dst = (seg == 0) ? q_out : (seg == 1) ? k_out : v_out;
        #pragma unroll
        for (int mt = 0; mt < 4; mt++) {
            #pragma unroll
            for (int nt = 0; nt < 4; nt++) {
                int row0  = brow + wm + mt * 16 + g;
                int colg  = bcol + wn + nt * 8 + 2 * tg;
                int colin = colg - seg * DMODEL;
                float b0 = bias[colg], b1 = bias[colg + 1];
                float fa0 = acc[mt][nt][0] + b0, fa1 = acc[mt][nt][1] + b1;
                float fb0 = acc[mt][nt][2] + b0, fb1 = acc[mt][nt][3] + b1;
                size_t d0 = (size_t)row0 * DMODEL + colin;
                size_t d1 = (size_t)(row0 + 8) * DMODEL + colin;
                *reinterpret_cast<uint32_t*>(&dst[d0]) =
                    h2_as_u32(__floats2half2_rn(fa0, fa1));
                *reinterpret_cast<uint32_t*>(&dst[d1]) =
                    h2_as_u32(__floats2half2_rn(fb0, fb1));
            }
        }
    }
}

// ---------------------------------------------------------------------------
// Tensor-core flash attention (causal), fp16 S + fp16 PV.
// 128-key KV load tiles as two 64-key sub-tiles (R14 shape).
// P computed directly in fp16 via ex2.approx.f16x2 (halves MUFU, kills the
// P->fp16 cvt; PV-path precision unchanged, l-sum error ~6e-5).
// ---------------------------------------------------------------------------
#define KS 72        // halves per K smem row: 36 words % 32 == 4 -> clean
#define VSTRIDE 72   // halves per V row
#define SUBOFF (64 * KS)   // halves offset of second sub-tile

__global__ __launch_bounds__(128)
void flash_attn_tc_kernel(const __half* __restrict__ gq,
                          const __half* __restrict__ gk,
                          const __half* __restrict__ gv,
                          __half* __restrict__ outa)
{
    __shared__ __half Kh[128 * KS];
    __shared__ __half Vs[128][VSTRIDE];

    const int qt   = (int)gridDim.x - 1 - (int)blockIdx.x;  // heavy tiles first
    const int h    = blockIdx.y;
    const int b    = blockIdx.z;
    const int tid  = threadIdx.x;
    const int warp = tid >> 5;
    const int lane = tid & 31;
    const int g    = lane >> 2;
    const int tg   = lane & 3;

    const uint32_t sKh = (uint32_t)__cvta_generic_to_shared(Kh);

    // Fold softmax scale and log2(e) into Q (softmax scale-invariant).
    const float qscale = 0.125f * 1.4426950408889634f;

    // --- Q fragments, fp16, m16n8k16 A layout; scale folded in ---
    uint32_t qf[4][4];
    {
        const __half* qbase =
            gq + (size_t)(b * SEQ + qt * 64 + warp * 16) * DMODEL + h * DHEAD;
        #pragma unroll
        for (int ks = 0; ks < 4; ks++) {
            #pragma unroll
            for (int j = 0; j < 4; j++) {
                int row = g + (j & 1) * 8;
                int col = ks * 16 + 2 * tg + (j & 2) * 4;
                uint32_t raw = *reinterpret_cast<const uint32_t*>(
                    &qbase[(size_t)row * DMODEL + col]);
                float2 f = __half22float2(u32_as_h2(raw));
                qf[ks][j] = h2_as_u32(
                    __floats2half2_rn(f.x * qscale, f.y * qscale));
            }
        }
    }

    float oacc[8][4];
    #pragma unroll
    for (int dt = 0; dt < 8; dt++)
        #pragma unroll
        for (int j = 0; j < 4; j++) oacc[dt][j] = 0.f;

    float m0 = -1e30f, m1 = -1e30f, l0 = 0.f, l1 = 0.f;

    const int n_kv2 = (qt >> 1) + 1;   // 128-key load tiles

    for (int kt2 = 0; kt2 < n_kv2; kt2++) {
        __syncthreads();
        // Cooperative copy of 128-key K and V tiles (uint4, 16 LDG/thread)
        #pragma unroll
        for (int it = 0; it < 8; it++) {
            int idx = it * 128 + tid;       // 0..1023
            int row = idx >> 3;             // key 0..127
            int c8  = idx & 7;              // 8-half group
            const size_t gidx =
                (size_t)(b * SEQ + kt2 * 128 + row) * DMODEL + h * DHEAD + c8 * 8;
            *reinterpret_cast<uint4*>(&Kh[row * KS + c8 * 8]) =
                *reinterpret_cast<const uint4*>(&gk[gidx]);
            *reinterpret_cast<uint4*>(&Vs[row][c8 * 8]) =
                *reinterpret_cast<const uint4*>(&gv[gidx]);
        }
        __syncthreads();

        #pragma unroll
        for (int half = 0; half < 2; half++) {
            const int kts = kt2 * 2 + half;   // 64-key sub-tile index
            if (kts > qt) break;              // fully masked -> skip exactly

            const uint32_t kbase = sKh + (uint32_t)(half * SUBOFF) * 2u;

            // --- S = Q·K^T (fp16 mma) ---
            float sacc[8][4];
            #pragma unroll
            for (int nt = 0; nt < 8; nt++)
                #pragma unroll
                for (int j = 0; j < 4; j++) sacc[nt][j] = 0.f;

            #pragma unroll
            for (int ks = 0; ks < 4; ks++) {
                #pragma unroll
                for (int ng = 0; ng < 4; ng++) {
                    uint32_t boff = (uint32_t)(
                        (ng * 16 + (lane & 15)) * KS +
                        ks * 16 + ((lane & 16) ? 8 : 0)) * 2u;
                    uint32_t b0, b1, b2, b3;
                    ldmatrix_x4(b0, b1, b2, b3, kbase + boff);
                    mma_f16(sacc[ng * 2],     qf[ks], b0, b2);
                    mma_f16(sacc[ng * 2 + 1], qf[ks], b1, b3);
                }
            }

            // --- causal mask on diagonal sub-tile ---
            if (kts == qt) {
                #pragma unroll
                for (int nt = 0; nt < 8; nt++) {
                    #pragma unroll
                    for (int j = 0; j < 4; j++) {
                        int row = warp * 16 + g + (j >> 1) * 8;
                        int col = nt * 8 + 2 * tg + (j & 1);
                        if (col > row) sacc[nt][j] = -1e30f;
                    }
                }
            }

            // --- online softmax (base-2) ---
            float mx0 = -1e30f, mx1 = -1e30f;
            #pragma unroll
            for (int nt = 0; nt < 8; nt++) {
                mx0 = fmaxf(mx0, fmaxf(sacc[nt][0], sacc[nt][1]));
                mx1 = fmaxf(mx1, fmaxf(sacc[nt][2], sacc[nt][3]));
            }
            mx0 = fmaxf(mx0, __shfl_xor_sync(0xffffffffu, mx0, 1));
            mx0 = fmaxf(mx0, __shfl_xor_sync(0xffffffffu, mx0, 2));
            mx1 = fmaxf(mx1, __shfl_xor_sync(0xffffffffu, mx1, 1));
            mx1 = fmaxf(mx1, __shfl_xor_sync(0xffffffffu, mx1, 2));

            float mn0 = fmaxf(m0, mx0);
            float mn1 = fmaxf(m1, mx1);
            float al0 = fast_exp2(m0 - mn0);
            float al1 = fast_exp2(m1 - mn1);

            // P in fp16 directly: ex2.approx.f16x2 on (s - m) pairs.
            uint32_t ph[8][2];
            float rs0 = 0.f, rs1 = 0.f;
            #pragma unroll
            for (int nt = 0; nt < 8; nt++) {
                uint32_t d01 = h2_as_u32(__floats2half2_rn(
                    sacc[nt][0] - mn0, sacc[nt][1] - mn0));
                uint32_t d23 = h2_as_u32(__floats2half2_rn(
                    sacc[nt][2] - mn1, sacc[nt][3] - mn1));
                uint32_t p01 = ex2_f16x2(d01);
                uint32_t p23 = ex2_f16x2(d23);
                ph[nt][0] = p01;
                ph[nt][1] = p23;
                float2 f01 = __half22float2(u32_as_h2(p01));
                float2 f23 = __half22float2(u32_as_h2(p23));
                rs0 += f01.x + f01.y;
                rs1 += f23.x + f23.y;
            }
            rs0 += __shfl_xor_sync(0xffffffffu, rs0, 1);
            rs0 += __shfl_xor_sync(0xffffffffu, rs0, 2);
            rs1 += __shfl_xor_sync(0xffffffffu, rs1, 1);
            rs1 += __shfl_xor_sync(0xffffffffu, rs1, 2);

            l0 = l0 * al0 + rs0;
            l1 = l1 * al1 + rs1;
            m0 = mn0;
            m1 = mn1;

            #pragma unroll
            for (int dt = 0; dt < 8; dt++) {
                oacc[dt][0] *= al0; oacc[dt][1] *= al0;
                oacc[dt][2] *= al1; oacc[dt][3] *= al1;
            }

            // --- O += P * V  (fp16 mma; P pairs already packed) ---
            #pragma unroll
            for (int ks = 0; ks < 4; ks++) {
                uint32_t pa[4];
                pa[0] = ph[2 * ks][0];
                pa[1] = ph[2 * ks][1];
                pa[2] = ph[2 * ks + 1][0];
                pa[3] = ph[2 * ks + 1][1];
                #pragma unroll
                for (int dp = 0; dp < 4; dp++) {
                    int krow = half * 64 + ks * 16 + (lane & 15);
                    int col  = dp * 16 + ((lane & 16) ? 8 : 0);
                    uint32_t addr =
                        (uint32_t)__cvta_generic_to_shared(&Vs[krow][col]);
                    uint32_t b0, b1, b2, b3;
                    ldmatrix_x4_trans(b0, b1, b2, b3, addr);
                    mma_f16(oacc[2 * dp],     pa, b0, b1);
                    mma_f16(oacc[2 * dp + 1], pa, b2, b3);
                }
            }
        }
    }

    // --- normalize + write fp16 ---
    const float inv0 = 1.f / l0;
    const float inv1 = 1.f / l1;
    const size_t obase =
        (size_t)(b * SEQ + qt * 64 + warp * 16) * DMODEL + h * DHEAD;
    #pragma unroll
    for (int dt = 0; dt < 8; dt++) {
        int col = dt * 8 + 2 * tg;
        size_t i0 = obase + (size_t)g * DMODEL + col;
        size_t i1 = obase + (size_t)(g + 8) * DMODEL + col;
        *reinterpret_cast<uint32_t*>(&outa[i0]) = h2_as_u32(
            __floats2half2_rn(oacc[dt][0] * inv0, oacc[dt][1] * inv0));
        *reinterpret_cast<uint32_t*>(&outa[i1]) = h2_as_u32(
            __floats2half2_rn(oacc[dt][2] * inv1, oacc[dt][3] * inv1));
    }
}

// ---------------------------------------------------------------------------
// Launch
// ---------------------------------------------------------------------------
extern "C" void kernel_launch(void* const* d_in, const int* in_sizes, int n_in,
                              void* d_out, int out_size)
{
    const float* x      = (const float*)d_in[0];
    const float* W_qkv  = (const float*)d_in[1];
    const float* b_qkv  = (const float*)d_in[2];
    const float* W_proj = (const float*)d_in[3];
    const float* b_proj = (const float*)d_in[4];
    float* out = (float*)d_out;

    void *p_x16, *p_wq16, *p_wp16, *p_q16, *p_k16, *p_v16, *p_at16;
    cudaGetSymbolAddress(&p_x16, g_x16);
    cudaGetSymbolAddress(&p_wq16, g_wq16);
    cudaGetSymbolAddress(&p_wp16, g_wp16);
    cudaGetSymbolAddress(&p_q16, g_q16);
    cudaGetSymbolAddress(&p_k16, g_k16);
    cudaGetSymbolAddress(&p_v16, g_v16);
    cudaGetSymbolAddress(&p_at16, g_at16);

    __half* x16  = (__half*)p_x16;
    __half* wq16 = (__half*)p_wq16;
    __half* wp16 = (__half*)p_wp16;
    __half* q16  = (__half*)p_q16;
    __half* k16  = (__half*)p_k16;
    __half* v16  = (__half*)p_v16;
    __half* at16 = (__half*)p_at16;

    // 0) fp32 -> fp16 input converts (streaming)
    cvt16_kernel<<<BT * DMODEL / 4 / 256, 256>>>(x, x16);
    cvt16_kernel<<<DMODEL * C3 / 4 / 256, 256>>>(W_qkv, wq16);
    cvt16_kernel<<<DMODEL * DMODEL / 4 / 256, 256>>>(W_proj, wp16);

    // 1) QKV projection (fp16 mma, 4-stage pipeline); writes Q/K/V fp16
    {
        dim3 grid(C3 / 128, BT / 128);
        gemm_f16_async_kernel<<<grid, 256>>>(x16, wq16, b_qkv,
                                             nullptr, BT, C3, DMODEL,
                                             1, q16, k16, v16);
    }

    // 2) Causal flash attention (128-key load tiles, f16x2 softmax)
    {
        dim3 grid(SEQ / 64, NHEADS, BATCH);
        flash_attn_tc_kernel<<<grid, 128>>>(q16, k16, v16, at16);
    }

    // 3) Output projection (fp16 mma, 4-stage pipeline, fp32 epilogue)
    {
        dim3 grid(DMODEL / 128, BT / 128);
        gemm_f16_async_kernel<<<grid, 256>>>(at16, wp16, b_proj,
                                             out, BT, DMODEL, DMODEL,
                                             0, nullptr, nullptr, nullptr);
    }
}

// round 16
// speedup vs baseline: 1.0859x; 1.0859x over previous
#include <cuda_runtime.h>
#include <cuda_fp16.h>
#include <cuda_bf16.h>
#include <math_constants.h>
#include <cstdint>
#include <cstring>

// Problem constants (fixed by reference setup_inputs)
#define BATCH   2
#define SEQ     4096
#define DMODEL  768
#define NHEADS  12
#define DHEAD   64
#define BT      (BATCH * SEQ)        // 8192
#define C3      (3 * DMODEL)         // 2304

// Scratch (device globals: allocation-free per harness rules)
__device__ __half g_x16[(size_t)BT * DMODEL];      // x fp16
__device__ __half g_wq16[(size_t)DMODEL * C3];     // W_qkv fp16
__device__ __half g_wp16[(size_t)DMODEL * DMODEL]; // W_proj fp16
__device__ __half g_q16[(size_t)BT * DMODEL];      // Q fp16
__device__ __half g_k16[(size_t)BT * DMODEL];      // K fp16
__device__ __half g_v16[(size_t)BT * DMODEL];      // V fp16
__device__ __half g_at16[(size_t)BT * DMODEL];     // att out fp16

// ---------------------------------------------------------------------------
// PTX helpers
// ---------------------------------------------------------------------------
__device__ __forceinline__ float fast_exp2(float x) {
    float y;
    asm("ex2.approx.f32 %0, %1;" : "=f"(y) : "f"(x));
    return y;
}

// Packed fp16x2 exp2 (one MUFU op for two values)
__device__ __forceinline__ uint32_t ex2_f16x2(uint32_t a) {
    uint32_t d;
    asm("ex2.approx.f16x2 %0, %1;" : "=r"(d) : "r"(a));
    return d;
}

__device__ __forceinline__ uint32_t h2_as_u32(__half2 h) {
    uint32_t r; memcpy(&r, &h, 4); return r;
}
__device__ __forceinline__ __half2 u32_as_h2(uint32_t r) {
    __half2 h; memcpy(&h, &r, 4); return h;
}

__device__ __forceinline__ void mma_f16(float c[4], const uint32_t a[4],
                                        uint32_t b0, uint32_t b1) {
    asm volatile(
        "mma.sync.aligned.m16n8k16.row.col.f32.f16.f16.f32 "
        "{%0,%1,%2,%3},{%4,%5,%6,%7},{%8,%9},{%0,%1,%2,%3};"
        : "+f"(c[0]), "+f"(c[1]), "+f"(c[2]), "+f"(c[3])
        : "r"(a[0]), "r"(a[1]), "r"(a[2]), "r"(a[3]), "r"(b0), "r"(b1));
}

__device__ __forceinline__ void ldmatrix_x4(uint32_t& r0, uint32_t& r1,
                                            uint32_t& r2, uint32_t& r3,
                                            uint32_t addr) {
    asm volatile(
        "ldmatrix.sync.aligned.m8n8.x4.shared.b16 {%0,%1,%2,%3}, [%4];"
        : "=r"(r0), "=r"(r1), "=r"(r2), "=r"(r3)
        : "r"(addr));
}

__device__ __forceinline__ void ldmatrix_x4_trans(uint32_t& r0, uint32_t& r1,
                                                  uint32_t& r2, uint32_t& r3,
                                                  uint32_t addr) {
    asm volatile(
        "ldmatrix.sync.aligned.m8n8.x4.trans.shared.b16 {%0,%1,%2,%3}, [%4];"
        : "=r"(r0), "=r"(r1), "=r"(r2), "=r"(r3)
        : "r"(addr));
}

__device__ __forceinline__ void cp_async16(uint32_t smem, const void* gmem) {
    asm volatile("cp.async.cg.shared.global [%0], [%1], 16;"
                 :: "r"(smem), "l"(gmem));
}
__device__ __forceinline__ void cp_commit() {
    asm volatile("cp.async.commit_group;");
}

// ---------------------------------------------------------------------------
// fp32 -> fp16 convert (streaming). One thread per float4.
// ---------------------------------------------------------------------------
__global__ __launch_bounds__(256)
void cvt16_kernel(const float* __restrict__ src, __half* __restrict__ dst)
{
    const size_t i4 = (size_t)blockIdx.x * 256 + threadIdx.x;
    float4 v = reinterpret_cast<const float4*>(src)[i4];
    __half h[4] = {__float2half_rn(v.x), __float2half_rn(v.y),
                   __float2half_rn(v.z), __float2half_rn(v.w)};
    uint2 u;
    memcpy(&u, h, 8);
    *reinterpret_cast<uint2*>(&dst[i4 * 4]) = u;
}

// ---------------------------------------------------------------------------
// fp16 GEMM (fp32 accum), cp.async DOUBLE buffer, BK=16 (proven R14 shape).
// mode 0: fp32 C store (+bias).
// mode 1: QKV fused epilogue — writes Q/K/V segments directly as fp16.
// ---------------------------------------------------------------------------
#define AST2 24     // halves per A smem row (16 + 8 pad); conflict-free
#define BST2 136    // halves per B smem row (128 + 8 pad)

__global__ __launch_bounds__(256, 2)
void gemm_f16_async_kernel(const __half* __restrict__ A16,
                           const __half* __restrict__ B16,
                           const float* __restrict__ bias,
                           float* __restrict__ Cmat,
                           int M, int N, int K,
                           int mode,
                           __half* __restrict__ q_out,
                           __half* __restrict__ k_out,
                           __half* __restrict__ v_out)
{
    __shared__ __half As[2][128 * AST2];
    __shared__ __half Bs[2][16 * BST2];

    const int tid  = threadIdx.x;
    const int warp = tid >> 5;
    const int lane = tid & 31;
    const int g    = lane >> 2;
    const int tg   = lane & 3;

    const int brow = blockIdx.y * 128;
    const int bcol = blockIdx.x * 128;
    const int wm   = (warp >> 2) * 64;
    const int wn   = (warp & 3) * 32;

    uint32_t sA[2] = {(uint32_t)__cvta_generic_to_shared(As[0]),
                      (uint32_t)__cvta_generic_to_shared(As[1])};
    uint32_t sB[2] = {(uint32_t)__cvta_generic_to_shared(Bs[0]),
                      (uint32_t)__cvta_generic_to_shared(Bs[1])};

    const int a_row = tid >> 1;          // 0..127
    const int a_c   = (tid & 1) * 8;     // halves 0 or 8
    const int b_row = tid >> 4;          // 0..15
    const int b_c   = (tid & 15) * 8;    // 0..120

    float acc[4][4][4];
    #pragma unroll
    for (int mt = 0; mt < 4; mt++)
        #pragma unroll
        for (int nt = 0; nt < 4; nt++)
            #pragma unroll
            for (int j = 0; j < 4; j++) acc[mt][nt][j] = 0.f;

    const int n_stages = K / 16;

    auto issue = [&](int s, int buf) {
        const int k0 = s * 16;
        cp_async16(sA[buf] + (a_row * AST2 + a_c) * 2,
                   &A16[(size_t)(brow + a_row) * K + k0 + a_c]);
        cp_async16(sB[buf] + (b_row * BST2 + b_c) * 2,
                   &B16[(size_t)(k0 + b_row) * N + bcol + b_c]);
        cp_commit();
    };

    issue(0, 0);

    for (int s = 0; s < n_stages; s++) {
        const int buf = s & 1;
        if (s + 1 < n_stages) {
            issue(s + 1, buf ^ 1);
            asm volatile("cp.async.wait_group 1;");
        } else {
            asm volatile("cp.async.wait_group 0;");
        }
        __syncthreads();

        uint32_t bf[2][4];
        #pragma unroll
        for (int ng = 0; ng < 2; ng++) {
            uint32_t boff = (uint32_t)(
                (lane & 15) * BST2 + wn + ng * 16 + ((lane & 16) ? 8 : 0)) * 2u;
            ldmatrix_x4_trans(bf[ng][0], bf[ng][1], bf[ng][2], bf[ng][3],
                              sB[buf] + boff);
        }
        #pragma unroll
        for (int mt = 0; mt < 4; mt++) {
            uint32_t af[4];
            uint32_t aoff = (uint32_t)(
                (wm + mt * 16 + (lane & 15)) * AST2 + ((lane & 16) ? 8 : 0)) * 2u;
            ldmatrix_x4(af[0], af[1], af[2], af[3], sA[buf] + aoff);
            #pragma unroll
            for (int ng = 0; ng < 2; ng++) {
                #pragma unroll
                for (int hh = 0; hh < 2; hh++) {
                    mma_f16(acc[mt][ng * 2 + hh], af,
                            bf[ng][2 * hh], bf[ng][2 * hh + 1]);
                }
            }
        }
        __syncthreads();
    }

    if (mode == 0) {
        #pragma unroll
        for (int mt = 0; mt < 4; mt++) {
            #pragma unroll
            for (int nt = 0; nt < 4; nt++) {
                int row0 = brow + wm + mt * 16 + g;
                int col  = bcol + wn + nt * 8 + 2 * tg;
                float b0 = bias[col], b1 = bias[col + 1];
                float2 v0 = make_float2(acc[mt][nt][0] + b0, acc[mt][nt][1] + b1);
                float2 v1 = make_float2(acc[mt][nt][2] + b0, acc[mt][nt][3] + b1);
                *reinterpret_cast<float2*>(&Cmat[(size_t)row0 * N + col])       = v0;
                *reinterpret_cast<float2*>(&Cmat[(size_t)(row0 + 8) * N + col]) = v1;
            }
        }
    } else {
        const int seg = bcol / DMODEL;   // 0=Q, 1=K, 2=V (uniform per block)
        __half* dst = (seg == 0) ? q_out : (seg == 1) ? k_out : v_out;
        #pragma unroll
        for (int mt = 0; mt < 4; mt++) {
            #pragma unroll
            for (int nt = 0; nt < 4; nt++) {
                int row0  = brow + wm + mt * 16 + g;
                int colg  = bcol + wn + nt * 8 + 2 * tg;
                int colin = colg - seg * DMODEL;
                float b0 = bias[colg], b1 = bias[colg + 1];
                float fa0 = acc[mt][nt][0] + b0, fa1 = acc[mt][nt][1] + b1;
                float fb0 = acc[mt][nt][2] + b0, fb1 = acc[mt][nt][3] + b1;
                size_t d0 = (size_t)row0 * DMODEL + colin;
                size_t d1 = (size_t)(row0 + 8) * DMODEL + colin;
                *reinterpret_cast<uint32_t*>(&dst[d0]) =
                    h2_as_u32(__floats2half2_rn(fa0, fa1));
                *reinterpret_cast<uint32_t*>(&dst[d1]) =
                    h2_as_u32(__floats2half2_rn(fb0, fb1));
            }
        }
    }
}

// ---------------------------------------------------------------------------
// Tensor-core flash attention (causal), fp16 S + fp16 PV, f16x2 softmax.
// cp.async PING-PONG over 64-key chunks: same 36.9 KB smem as R14 (no
// occupancy loss), load of chunk kt+1 overlapped with compute of chunk kt.
// One barrier per 64 keys.
// ---------------------------------------------------------------------------
#define KS 72        // halves per K smem row: 36 words % 32 == 4 -> clean
#define VSTRIDE 72   // halves per V row

__global__ __launch_bounds__(128)
void flash_attn_tc_kernel(const __half* __restrict__ gq,
                          const __half* __restrict__ gk,
                          const __half* __restrict__ gv,
                          __half* __restrict__ outa)
{
    __shared__ __half Kh[2][64 * KS];
    __shared__ __half Vs[2][64 * VSTRIDE];

    const int qt   = (int)gridDim.x - 1 - (int)blockIdx.x;  // heavy tiles first
    const int h    = blockIdx.y;
    const int b    = blockIdx.z;
    const int tid  = threadIdx.x;
    const int warp = tid >> 5;
    const int lane = tid & 31;
    const int g    = lane >> 2;
    const int tg   = lane & 3;

    const uint32_t aKh[2] = {(uint32_t)__cvta_generic_to_shared(Kh[0]),
                             (uint32_t)__cvta_generic_to_shared(Kh[1])};
    const uint32_t aVs[2] = {(uint32_t)__cvta_generic_to_shared(Vs[0]),
                             (uint32_t)__cvta_generic_to_shared(Vs[1])};

    // Fold softmax scale and log2(e) into Q (softmax scale-invariant).
    const float qscale = 0.125f * 1.4426950408889634f;

    // --- Q fragments, fp16, m16n8k16 A layout; scale folded in ---
    uint32_t qf[4][4];
    {
        const __half* qbase =
            gq + (size_t)(b * SEQ + qt * 64 + warp * 16) * DMODEL + h * DHEAD;
        #pragma unroll
        for (int ks = 0; ks < 4; ks++) {
            #pragma unroll
            for (int j = 0; j < 4; j++) {
                int row = g + (j & 1) * 8;
                int col = ks * 16 + 2 * tg + (j & 2) * 4;
                uint32_t raw = *reinterpret_cast<const uint32_t*>(
                    &qbase[(size_t)row * DMODEL + col]);
                float2 f = __half22float2(u32_as_h2(raw));
                qf[ks][j] = h2_as_u32(
                    __floats2half2_rn(f.x * qscale, f.y * qscale));
            }
        }
    }

    // 64-key chunk load: 8 cp.async16 per thread
    auto issue = [&](int kt, int buf) {
        #pragma unroll
        for (int it = 0; it < 4; it++) {
            int idx = it * 128 + tid;       // 0..511
            int row = idx >> 3;             // key 0..63
            int c8  = idx & 7;              // 8-half group
            const size_t gidx =
                (size_t)(b * SEQ + kt * 64 + row) * DMODEL + h * DHEAD + c8 * 8;
            uint32_t soff = (uint32_t)(row * KS + c8 * 8) * 2u;
            cp_async16(aKh[buf] + soff, &gk[gidx]);
            cp_async16(aVs[buf] + (uint32_t)(row * VSTRIDE + c8 * 8) * 2u,
                       &gv[gidx]);
        }
        cp_commit();
    };

    float oacc[8][4];
    #pragma unroll
    for (int dt = 0; dt < 8; dt++)
        #pragma unroll
        for (int j = 0; j < 4; j++) oacc[dt][j] = 0.f;

    float m0 = -1e30f, m1 = -1e30f, l0 = 0.f, l1 = 0.f;

    issue(0, 0);

    for (int kt = 0; kt <= qt; kt++) {
        const int buf = kt & 1;
        asm volatile("cp.async.wait_group 0;");
        __syncthreads();     // chunk kt visible; all warps past compute(kt-1)
        if (kt < qt) issue(kt + 1, buf ^ 1);

        // --- S = Q·K^T (fp16 mma) ---
        float sacc[8][4];
        #pragma unroll
        for (int nt = 0; nt < 8; nt++)
            #pragma unroll
            for (int j = 0; j < 4; j++) sacc[nt][j] = 0.f;

        #pragma unroll
        for (int ks = 0; ks < 4; ks++) {
            #pragma unroll
            for (int ng = 0; ng < 4; ng++) {
                uint32_t boff = (uint32_t)(
                    (ng * 16 + (lane & 15)) * KS +
                    ks * 16 + ((lane & 16) ? 8 : 0)) * 2u;
                uint32_t b0, b1, b2, b3;
                ldmatrix_x4(b0, b1, b2, b3, aKh[buf] + boff);
                mma_f16(sacc[ng * 2],     qf[ks], b0, b2);
                mma_f16(sacc[ng * 2 + 1], qf[ks], b1, b3);
            }
        }

        // --- causal mask on diagonal chunk ---
        if (kt == qt) {
            #pragma unroll
            for (int nt = 0; nt < 8; nt++) {
                #pragma unroll
                for (int j = 0; j < 4; j++) {
                    int row = warp * 16 + g + (j >> 1) * 8;
                    int col = nt * 8 + 2 * tg + (j & 1);
                    if (col > row) sacc[nt][j] = -1e30f;
                }
            }
        }

        // --- online softmax (base-2) ---
        float mx0 = -1e30f, mx1 = -1e30f;
        #pragma unroll
        for (int nt = 0; nt < 8; nt++) {
            mx0 = fmaxf(mx0, fmaxf(sacc[nt][0], sacc[nt][1]));
            mx1 = fmaxf(mx1, fmaxf(sacc[nt][2], sacc[nt][3]));
        }
        mx0 = fmaxf(mx0, __shfl_xor_sync(0xffffffffu, mx0, 1));
        mx0 = fmaxf(mx0, __shfl_xor_sync(0xffffffffu, mx0, 2));
        mx1 = fmaxf(mx1, __shfl_xor_sync(0xffffffffu, mx1, 1));
        mx1 = fmaxf(mx1, __shfl_xor_sync(0xffffffffu, mx1, 2));

        float mn0 = fmaxf(m0, mx0);
        float mn1 = fmaxf(m1, mx1);
        float al0 = fast_exp2(m0 - mn0);
        float al1 = fast_exp2(m1 - mn1);

        // P in fp16 directly: ex2.approx.f16x2 on (s - m) pairs.
        uint32_t ph[8][2];
        float rs0 = 0.f, rs1 = 0.f;
        #pragma unroll
        for (int nt = 0; nt < 8; nt++) {
            uint32_t d01 = h2_as_u32(__floats2half2_rn(
                sacc[nt][0] - mn0, sacc[nt][1] - mn0));
            uint32_t d23 = h2_as_u32(__floats2half2_rn(
                sacc[nt][2] - mn1, sacc[nt][3] - mn1));
            uint32_t p01 = ex2_f16x2(d01);
            uint32_t p23 = ex2_f16x2(d23);
            ph[nt][0] = p01;
            ph[nt][1] = p23;
            float2 f01 = __half22float2(u32_as_h2(p01));
            float2 f23 = __half22float2(u32_as_h2(p23));
            rs0 += f01.x + f01.y;
            rs1 += f23.x + f23.y;
        }
        rs0 += __shfl_xor_sync(0xffffffffu, rs0, 1);
        rs0 += __shfl_xor_sync(0xffffffffu, rs0, 2);
        rs1 += __shfl_xor_sync(0xffffffffu, rs1, 1);
        rs1 += __shfl_xor_sync(0xffffffffu, rs1, 2);

        l0 = l0 * al0 + rs0;
        l1 = l1 * al1 + rs1;
        m0 = mn0;
        m1 = mn1;

        #pragma unroll
        for (int dt = 0; dt < 8; dt++) {
            oacc[dt][0] *= al0; oacc[dt][1] *= al0;
            oacc[dt][2] *= al1; oacc[dt][3] *= al1;
        }

        // --- O += P * V  (fp16 mma; P pairs already packed) ---
        #pragma unroll
        for (int ks = 0; ks < 4; ks++) {
            uint32_t pa[4];
            pa[0] = ph[2 * ks][0];
            pa[1] = ph[2 * ks][1];
            pa[2] = ph[2 * ks + 1][0];
            pa[3] = ph[2 * ks + 1][1];
            #pragma unroll
            for (int dp = 0; dp < 4; dp++) {
                int krow = ks * 16 + (lane & 15);
                int col  = dp * 16 + ((lane & 16) ? 8 : 0);
                uint32_t addr = aVs[buf] +
                    (uint32_t)(krow * VSTRIDE + col) * 2u;
                uint32_t b0, b1, b2, b3;
                ldmatrix_x4_trans(b0, b1, b2, b3, addr);
                mma_f16(oacc[2 * dp],     pa, b0, b1);
                mma_f16(oacc[2 * dp + 1], pa, b2, b3);
            }
        }
    }

    // --- normalize + write fp16 ---
    const float inv0 = 1.f / l0;
    const float inv1 = 1.f / l1;
    const size_t obase =
        (size_t)(b * SEQ + qt * 64 + warp * 16) * DMODEL + h * DHEAD;
    #pragma unroll
    for (int dt = 0; dt < 8; dt++) {
        int col = dt * 8 + 2 * tg;
        size_t i0 = obase + (size_t)g * DMODEL + col;
        size_t i1 = obase + (size_t)(g + 8) * DMODEL + col;
        *reinterpret_cast<uint32_t*>(&outa[i0]) = h2_as_u32(
            __floats2half2_rn(oacc[dt][0] * inv0, oacc[dt][1] * inv0));
        *reinterpret_cast<uint32_t*>(&outa[i1]) = h2_as_u32(
            __floats2half2_rn(oacc[dt][2] * inv1, oacc[dt][3] * inv1));
    }
}

// ---------------------------------------------------------------------------
// Launch
// ---------------------------------------------------------------------------
extern "C" void kernel_launch(void* const* d_in, const int* in_sizes, int n_in,
                              void* d_out, int out_size)
{
    const float* x      = (const float*)d_in[0];
    const float* W_qkv  = (const float*)d_in[1];
    const float* b_qkv  = (const float*)d_in[2];
    const float* W_proj = (const float*)d_in[3];
    const float* b_proj = (const float*)d_in[4];
    float* out = (float*)d_out;

    void *p_x16, *p_wq16, *p_wp16, *p_q16, *p_k16, *p_v16, *p_at16;
    cudaGetSymbolAddress(&p_x16, g_x16);
    cudaGetSymbolAddress(&p_wq16, g_wq16);
    cudaGetSymbolAddress(&p_wp16, g_wp16);
    cudaGetSymbolAddress(&p_q16, g_q16);
    cudaGetSymbolAddress(&p_k16, g_k16);
    cudaGetSymbolAddress(&p_v16, g_v16);
    cudaGetSymbolAddress(&p_at16, g_at16);

    __half* x16  = (__half*)p_x16;
    __half* wq16 = (__half*)p_wq16;
    __half* wp16 = (__half*)p_wp16;
    __half* q16  = (__half*)p_q16;
    __half* k16  = (__half*)p_k16;
    __half* v16  = (__half*)p_v16;
    __half* at16 = (__half*)p_at16;

    // 0) fp32 -> fp16 input converts (streaming)
    cvt16_kernel<<<BT * DMODEL / 4 / 256, 256>>>(x, x16);
    cvt16_kernel<<<DMODEL * C3 / 4 / 256, 256>>>(W_qkv, wq16);
    cvt16_kernel<<<DMODEL * DMODEL / 4 / 256, 256>>>(W_proj, wp16);

    // 1) QKV projection (fp16 mma, 2-stage pipeline); writes Q/K/V fp16
    {
        dim3 grid(C3 / 128, BT / 128);
        gemm_f16_async_kernel<<<grid, 256>>>(x16, wq16, b_qkv,
                                             nullptr, BT, C3, DMODEL,
                                             1, q16, k16, v16);
    }

    // 2) Causal flash attention (cp.async ping-pong, f16x2 softmax)
    {
        dim3 grid(SEQ / 64, NHEADS, BATCH);
        flash_attn_tc_kernel<<<grid, 128>>>(q16, k16, v16, at16);
    }

    // 3) Output projection (fp16 mma, 2-stage pipeline, fp32 epilogue)
    {
        dim3 grid(DMODEL / 128, BT / 128);
        gemm_f16_async_kernel<<<grid, 256>>>(at16, wp16, b_proj,
                                             out, BT, DMODEL, DMODEL,
                                             0, nullptr, nullptr, nullptr);
    }
}